// round 1
// baseline (speedup 1.0000x reference)
#include <cuda_runtime.h>
#include <math.h>

#define LLEAF 2048
#define NNODES 4095
#define MEM 150
#define IN_DIM 300
#define HIDD 50
#define NCLS 5
#define HSTR 152

// Scratch (device globals: no allocations allowed)
__device__ float g_C[2][NNODES][HSTR];
__device__ float g_H[2][NNODES][HSTR];
__device__ float g_s[2][NNODES];
__device__ float g_red[4];              // maxl, invsuml, maxr, invsumr
__device__ float g_part[2][32][HSTR];   // partial attention sums (deterministic)

__device__ __forceinline__ float sigf(float x) { return 1.f / (1.f + expf(-x)); }

// ---------------------------------------------------------------------------
// Leaf kernel: 16 leaves per block. Thread j<150 computes gate columns
// (j, 150+j, 300+j) of iou = x @ W_ioux + b_ioux + b_iouh for all 16 leaves.
// ---------------------------------------------------------------------------
__global__ __launch_bounds__(160) void leaf_kernel(
    const int* __restrict__ ltok, const int* __restrict__ rtok,
    const float* __restrict__ emb, const float* __restrict__ Wx,
    const float* __restrict__ bx, const float* __restrict__ bh)
{
    __shared__ float xs[16 * IN_DIM];
    __shared__ int toks[16];
    const int tid = threadIdx.x;
    const int t = blockIdx.x >> 7;       // tree (0/1), 128 blocks per tree
    const int g = blockIdx.x & 127;
    const int leaf0 = g * 16;
    const int* tok = t ? rtok : ltok;

    if (tid < 16) toks[tid] = tok[leaf0 + tid];
    __syncthreads();
    for (int idx = tid; idx < 16 * IN_DIM; idx += 160) {
        int r = idx / IN_DIM, k = idx - r * IN_DIM;
        xs[idx] = emb[toks[r] * IN_DIM + k];
    }
    __syncthreads();

    const int j = tid;
    if (j < MEM) {
        float ai[16], ao[16], au[16];
#pragma unroll
        for (int r = 0; r < 16; r++) { ai[r] = 0.f; ao[r] = 0.f; au[r] = 0.f; }
        for (int k = 0; k < IN_DIM; k++) {
            float wi = Wx[k * 450 + j];
            float wo = Wx[k * 450 + 150 + j];
            float wu = Wx[k * 450 + 300 + j];
#pragma unroll
            for (int r = 0; r < 16; r++) {
                float xv = xs[r * IN_DIM + k];
                ai[r] = fmaf(xv, wi, ai[r]);
                ao[r] = fmaf(xv, wo, ao[r]);
                au[r] = fmaf(xv, wu, au[r]);
            }
        }
        float bi = bx[j] + bh[j];
        float bo = bx[150 + j] + bh[150 + j];
        float bu = bx[300 + j] + bh[300 + j];
#pragma unroll
        for (int r = 0; r < 16; r++) {
            float iv = sigf(ai[r] + bi);
            float ov = sigf(ao[r] + bo);
            float uv = tanhf(au[r] + bu);
            float c = iv * uv;
            g_C[t][leaf0 + r][j] = c;
            g_H[t][leaf0 + r][j] = ov * tanhf(c);
        }
    }
}

// ---------------------------------------------------------------------------
// Level kernel: 8 internal nodes (across both trees) per block.
// Out-of-range units clamp to the last unit (duplicate identical writes).
// ---------------------------------------------------------------------------
__global__ __launch_bounds__(160) void level_kernel(
    const int* __restrict__ lidx, const int* __restrict__ ridx,
    const float* __restrict__ Wh, const float* __restrict__ bh,
    const float* __restrict__ Wf, const float* __restrict__ bf,
    int e0, int P)
{
    __shared__ float shl[8][MEM], shr[8][MEM], shs[8][MEM];
    __shared__ int s_li[8], s_ri[8], s_t[8], s_k[8];
    const int tid = threadIdx.x;
    const int U = 2 * P;

    if (tid < 8) {
        int u = blockIdx.x * 8 + tid;
        if (u >= U) u = U - 1;
        int t = u / P;
        int e = e0 + (u - t * P);
        s_t[tid] = t;
        s_k[tid] = LLEAF + e;
        s_li[tid] = lidx[e];
        s_ri[tid] = ridx[e];
    }
    __syncthreads();
    for (int idx = tid; idx < 8 * MEM; idx += 160) {
        int r = idx / MEM, k = idx - r * MEM;
        float a = g_H[s_t[r]][s_li[r]][k];
        float b = g_H[s_t[r]][s_ri[r]][k];
        shl[r][k] = a; shr[r][k] = b; shs[r][k] = a + b;
    }
    __syncthreads();

    const int j = tid;
    if (j < MEM) {
        float ai[8], ao[8], au[8], afl[8], afr[8];
#pragma unroll
        for (int r = 0; r < 8; r++) { ai[r] = ao[r] = au[r] = afl[r] = afr[r] = 0.f; }
        for (int k = 0; k < MEM; k++) {
            float wi = Wh[k * 450 + j];
            float wo = Wh[k * 450 + 150 + j];
            float wu = Wh[k * 450 + 300 + j];
            float wf = Wf[k * 150 + j];
#pragma unroll
            for (int r = 0; r < 8; r++) {
                float hs = shs[r][k];
                ai[r]  = fmaf(hs, wi, ai[r]);
                ao[r]  = fmaf(hs, wo, ao[r]);
                au[r]  = fmaf(hs, wu, au[r]);
                afl[r] = fmaf(shl[r][k], wf, afl[r]);
                afr[r] = fmaf(shr[r][k], wf, afr[r]);
            }
        }
        float bi = bh[j], bo = bh[150 + j], bu = bh[300 + j], bfv = bf[j];
#pragma unroll
        for (int r = 0; r < 8; r++) {
            float iv = sigf(ai[r] + bi);
            float ov = sigf(ao[r] + bo);
            float uv = tanhf(au[r] + bu);
            float fl = sigf(afl[r] + bfv);
            float fr = sigf(afr[r] + bfv);
            int t = s_t[r];
            float c = iv * uv + fl * g_C[t][s_li[r]][j] + fr * g_C[t][s_ri[r]][j];
            g_C[t][s_k[r]][j] = c;
            g_H[t][s_k[r]][j] = ov * tanhf(c);
        }
    }
}

// ---------------------------------------------------------------------------
// Attention scores: one warp per (side, node) dot product of length 150.
// side 0: s_l[j] = Hl_last . Hr[j]; side 1: s_r[i] = Hr_last . Hl[i]
// ---------------------------------------------------------------------------
__global__ void score_kernel()
{
    int wid = (blockIdx.x * blockDim.x + threadIdx.x) >> 5;
    int lane = threadIdx.x & 31;
    if (wid >= 2 * NNODES) return;
    int side = wid / NNODES;
    int node = wid - side * NNODES;
    int qt = side;
    int rt = 1 - side;
    float sum = 0.f;
    for (int k = lane; k < MEM; k += 32)
        sum += g_H[qt][NNODES - 1][k] * g_H[rt][node][k];
#pragma unroll
    for (int off = 16; off; off >>= 1) sum += __shfl_xor_sync(0xffffffffu, sum, off);
    if (lane == 0) g_s[side][node] = sum;
}

// ---------------------------------------------------------------------------
// Softmax normalizers (max + 1/sumexp) for both score vectors. One block.
// ---------------------------------------------------------------------------
__global__ void reduce_kernel()
{
    __shared__ float red[8];
    __shared__ float bc;
    const int tid = threadIdx.x;
    const int lane = tid & 31, w = tid >> 5;
    for (int side = 0; side < 2; side++) {
        float m = -1e30f;
        for (int i = tid; i < NNODES; i += 256) m = fmaxf(m, g_s[side][i]);
#pragma unroll
        for (int off = 16; off; off >>= 1) m = fmaxf(m, __shfl_xor_sync(0xffffffffu, m, off));
        if (lane == 0) red[w] = m;
        __syncthreads();
        if (tid == 0) {
            float mm = red[0];
            for (int i = 1; i < 8; i++) mm = fmaxf(mm, red[i]);
            bc = mm;
        }
        __syncthreads();
        float mx = bc;
        float s = 0.f;
        for (int i = tid; i < NNODES; i += 256) s += expf(g_s[side][i] - mx);
#pragma unroll
        for (int off = 16; off; off >>= 1) s += __shfl_xor_sync(0xffffffffu, s, off);
        __syncthreads();
        if (lane == 0) red[w] = s;
        __syncthreads();
        if (tid == 0) {
            float tot = 0.f;
            for (int i = 0; i < 8; i++) tot += red[i];
            g_red[side * 2] = mx;
            g_red[side * 2 + 1] = 1.f / tot;
        }
        __syncthreads();
    }
}

// ---------------------------------------------------------------------------
// Weighted sums: beta_last = softmax(s_l) @ Hr; alpha_last = softmax(s_r) @ Hl.
// Deterministic: each block writes its own partial slot; summed later in order.
// ---------------------------------------------------------------------------
#define ACHUNK 128
__global__ __launch_bounds__(160) void attsum_kernel()
{
    __shared__ float w[ACHUNK];
    const int side = blockIdx.y;
    const int rt = 1 - side;
    const int tid = threadIdx.x;
    const int j0 = blockIdx.x * ACHUNK;
    float mx = g_red[side * 2], inv = g_red[side * 2 + 1];
    for (int jj = tid; jj < ACHUNK; jj += 160) {
        int jg = j0 + jj;
        w[jj] = (jg < NNODES) ? expf(g_s[side][jg] - mx) * inv : 0.f;
    }
    __syncthreads();
    if (tid < MEM) {
        float p = 0.f;
        int lim = min(ACHUNK, NNODES - j0);
        for (int jj = 0; jj < lim; jj++)
            p = fmaf(w[jj], g_H[rt][j0 + jj][tid], p);
        g_part[side][blockIdx.x][tid] = p;
    }
}

// ---------------------------------------------------------------------------
// Final head: v_l/v_r last rows, feature MLP, log_softmax. One block.
// ---------------------------------------------------------------------------
__global__ __launch_bounds__(160) void final_kernel(
    const float* __restrict__ Wa, const float* __restrict__ ba,
    const float* __restrict__ Wwh, const float* __restrict__ bwh,
    const float* __restrict__ Wwp, const float* __restrict__ bwp,
    float* __restrict__ out)
{
    __shared__ float q0[MEM], q1[MEM], beta[MEM], alpha[MEM];
    __shared__ float slh[MEM], srh[MEM], hid[HIDD], lg[NCLS];
    const int tid = threadIdx.x;
    if (tid < MEM) {
        q0[tid] = g_H[0][NNODES - 1][tid];
        q1[tid] = g_H[1][NNODES - 1][tid];
        float b = 0.f, a = 0.f;
        for (int p = 0; p < 32; p++) { b += g_part[0][p][tid]; a += g_part[1][p][tid]; }
        beta[tid] = b; alpha[tid] = a;
    }
    __syncthreads();
    if (tid < MEM) {
        float lh = ba[tid], rh = ba[tid];
        for (int k = 0; k < MEM; k++) {
            float w1 = Wa[k * MEM + tid];
            float w2 = Wa[(MEM + k) * MEM + tid];
            lh += q0[k] * w1 + beta[k] * w2;
            rh += q1[k] * w1 + alpha[k] * w2;
        }
        slh[tid] = lh; srh[tid] = rh;
    }
    __syncthreads();
    if (tid < HIDD) {
        float acc = bwh[tid];
        for (int k = 0; k < MEM; k++) {
            float pr = slh[k] * srh[k];
            float ad = fabsf(slh[k] - srh[k]);
            acc += pr * Wwh[k * HIDD + tid] + ad * Wwh[(MEM + k) * HIDD + tid];
        }
        hid[tid] = 1.f / (1.f + expf(-acc));
    }
    __syncthreads();
    if (tid < NCLS) {
        float v = bwp[tid];
        for (int m = 0; m < HIDD; m++) v += hid[m] * Wwp[m * NCLS + tid];
        lg[tid] = v;
    }
    __syncthreads();
    if (tid < NCLS) {
        float mx = lg[0];
        for (int c = 1; c < NCLS; c++) mx = fmaxf(mx, lg[c]);
        float s = 0.f;
        for (int c = 0; c < NCLS; c++) s += expf(lg[c] - mx);
        out[tid] = lg[tid] - mx - logf(s);
    }
}

// ---------------------------------------------------------------------------
extern "C" void kernel_launch(void* const* d_in, const int* in_sizes, int n_in,
                              void* d_out, int out_size)
{
    const int*   ltok = (const int*)d_in[0];
    const int*   rtok = (const int*)d_in[1];
    const int*   lidx = (const int*)d_in[2];
    const int*   ridx = (const int*)d_in[3];
    const float* emb  = (const float*)d_in[4];
    const float* Wx   = (const float*)d_in[5];
    const float* bx   = (const float*)d_in[6];
    const float* Wh   = (const float*)d_in[7];
    const float* bhh  = (const float*)d_in[8];
    // d_in[9] = W_fx, d_in[10] = b_fx : unused by the reference
    const float* Wf   = (const float*)d_in[11];
    const float* bf   = (const float*)d_in[12];
    const float* Wa   = (const float*)d_in[13];
    const float* ba   = (const float*)d_in[14];
    const float* Wwh  = (const float*)d_in[15];
    const float* bwh  = (const float*)d_in[16];
    const float* Wwp  = (const float*)d_in[17];
    const float* bwp  = (const float*)d_in[18];
    float* out = (float*)d_out;

    leaf_kernel<<<256, 160>>>(ltok, rtok, emb, Wx, bx, bhh);

    static const int e0s[11] = {0, 1024, 1536, 1792, 1920, 1984, 2016, 2032, 2040, 2044, 2046};
    static const int Ps[11]  = {1024, 512, 256, 128, 64, 32, 16, 8, 4, 2, 1};
    for (int l = 0; l < 11; l++) {
        int blocks = (2 * Ps[l] + 7) / 8;
        level_kernel<<<blocks, 160>>>(lidx, ridx, Wh, bhh, Wf, bf, e0s[l], Ps[l]);
    }

    score_kernel<<<1024, 256>>>();
    reduce_kernel<<<1, 256>>>();
    attsum_kernel<<<dim3(32, 2), 160>>>();
    final_kernel<<<1, 160>>>(Wa, ba, Wwh, bwh, Wwp, bwp, out);
}

// round 2
// speedup vs baseline: 1.7998x; 1.7998x over previous
#include <cuda_runtime.h>
#include <math.h>

#define LLEAF 2048
#define NNODES 4095
#define MEM 150
#define IN_DIM 300
#define HIDD 50
#define NCLS 5
#define HSTR 152

typedef unsigned long long ull;

// Scratch (device globals: no allocations allowed)
__device__ float g_C[2][NNODES][HSTR];
__device__ float g_H[2][NNODES][HSTR];
__device__ float g_s[2][NNODES];
__device__ float g_red[4];              // maxl, invsuml, maxr, invsumr
__device__ float g_part[2][32][HSTR];   // partial attention sums (deterministic)

__device__ __forceinline__ float sigf(float x) { return 1.f / (1.f + expf(-x)); }

__device__ __forceinline__ ull pack2(float a, float b) {
    ull r; asm("mov.b64 %0, {%1,%2};" : "=l"(r) : "f"(a), "f"(b)); return r;
}
__device__ __forceinline__ void ffma2(ull& d, ull a, ull b) {
    asm("fma.rn.f32x2 %0, %1, %2, %0;" : "+l"(d) : "l"(a), "l"(b));
}
__device__ __forceinline__ float2 unpack2(ull v) {
    float2 f; asm("mov.b64 {%0,%1}, %2;" : "=f"(f.x), "=f"(f.y) : "l"(v)); return f;
}

// ---------------------------------------------------------------------------
// Leaf kernel: 16 leaves per block, transposed shared activations, f32x2 FMA.
// Thread j<150 computes gate columns (j, 150+j, 300+j) for all 16 leaves.
// ---------------------------------------------------------------------------
#define RLEAF 16
#define XPAD 18
__global__ __launch_bounds__(160, 4) void leaf_kernel(
    const int* __restrict__ ltok, const int* __restrict__ rtok,
    const float* __restrict__ emb, const float* __restrict__ Wx,
    const float* __restrict__ bx, const float* __restrict__ bh)
{
    __shared__ __align__(16) float xs[IN_DIM][XPAD];   // [k][leaf]
    __shared__ int toks[RLEAF];
    const int tid = threadIdx.x;
    const int t = blockIdx.x >> 7;       // tree (0/1), 128 blocks per tree
    const int g = blockIdx.x & 127;
    const int leaf0 = g * RLEAF;
    const int* tok = t ? rtok : ltok;

    if (tid < RLEAF) toks[tid] = tok[leaf0 + tid];
    __syncthreads();
    for (int idx = tid; idx < RLEAF * IN_DIM; idx += 160) {
        int r = idx / IN_DIM, k = idx - r * IN_DIM;
        xs[k][r] = emb[toks[r] * IN_DIM + k];
    }
    __syncthreads();

    const int j = tid;
    if (j < MEM) {
        ull ai[RLEAF/2], ao[RLEAF/2], au[RLEAF/2];
#pragma unroll
        for (int p = 0; p < RLEAF/2; p++) { ai[p] = 0ull; ao[p] = 0ull; au[p] = 0ull; }
#pragma unroll 2
        for (int k = 0; k < IN_DIM; k++) {
            float wi = Wx[k * 450 + j];
            float wo = Wx[k * 450 + 150 + j];
            float wu = Wx[k * 450 + 300 + j];
            ull wi2 = pack2(wi, wi), wo2 = pack2(wo, wo), wu2 = pack2(wu, wu);
            const ull* px = reinterpret_cast<const ull*>(&xs[k][0]);
#pragma unroll
            for (int p = 0; p < RLEAF/2; p++) {
                ull xv = px[p];
                ffma2(ai[p], wi2, xv);
                ffma2(ao[p], wo2, xv);
                ffma2(au[p], wu2, xv);
            }
        }
        float bi = bx[j] + bh[j];
        float bo = bx[150 + j] + bh[150 + j];
        float bu = bx[300 + j] + bh[300 + j];
#pragma unroll
        for (int p = 0; p < RLEAF/2; p++) {
            float2 fi = unpack2(ai[p]), fo = unpack2(ao[p]), fu = unpack2(au[p]);
            {
                float iv = sigf(fi.x + bi), ov = sigf(fo.x + bo), uv = tanhf(fu.x + bu);
                float c = iv * uv;
                g_C[t][leaf0 + 2*p][j] = c;
                g_H[t][leaf0 + 2*p][j] = ov * tanhf(c);
            }
            {
                float iv = sigf(fi.y + bi), ov = sigf(fo.y + bo), uv = tanhf(fu.y + bu);
                float c = iv * uv;
                g_C[t][leaf0 + 2*p + 1][j] = c;
                g_H[t][leaf0 + 2*p + 1][j] = ov * tanhf(c);
            }
        }
    }
}

// ---------------------------------------------------------------------------
// Level kernel: R internal nodes per block (R | 2P exactly), transposed
// shared activations, f32x2 FMA.
// ---------------------------------------------------------------------------
template <int R>
__global__ __launch_bounds__(160, 4) void level_kernel(
    const int* __restrict__ lidx, const int* __restrict__ ridx,
    const float* __restrict__ Wh, const float* __restrict__ bh,
    const float* __restrict__ Wf, const float* __restrict__ bf,
    int e0, int P)
{
    __shared__ __align__(16) float ss[MEM][R + 2], sl[MEM][R + 2], sr[MEM][R + 2];
    __shared__ int s_li[R], s_ri[R], s_t[R], s_k[R];
    const int tid = threadIdx.x;

    if (tid < R) {
        int u = blockIdx.x * R + tid;
        int t = u / P;
        int e = e0 + (u - t * P);
        s_t[tid] = t;
        s_k[tid] = LLEAF + e;
        s_li[tid] = lidx[e];
        s_ri[tid] = ridx[e];
    }
    __syncthreads();
    for (int idx = tid; idx < R * MEM; idx += 160) {
        int r = idx / MEM, k = idx - r * MEM;
        float a = g_H[s_t[r]][s_li[r]][k];
        float b = g_H[s_t[r]][s_ri[r]][k];
        sl[k][r] = a; sr[k][r] = b; ss[k][r] = a + b;
    }
    __syncthreads();

    const int j = tid;
    if (j < MEM) {
        ull ai[R/2], ao[R/2], au[R/2], afl[R/2], afr[R/2];
#pragma unroll
        for (int p = 0; p < R/2; p++) { ai[p] = ao[p] = au[p] = afl[p] = afr[p] = 0ull; }
#pragma unroll 2
        for (int k = 0; k < MEM; k++) {
            float wi = Wh[k * 450 + j];
            float wo = Wh[k * 450 + 150 + j];
            float wu = Wh[k * 450 + 300 + j];
            float wf = Wf[k * 150 + j];
            ull wi2 = pack2(wi, wi), wo2 = pack2(wo, wo);
            ull wu2 = pack2(wu, wu), wf2 = pack2(wf, wf);
            const ull* ps = reinterpret_cast<const ull*>(&ss[k][0]);
            const ull* pl = reinterpret_cast<const ull*>(&sl[k][0]);
            const ull* pr = reinterpret_cast<const ull*>(&sr[k][0]);
#pragma unroll
            for (int p = 0; p < R/2; p++) {
                ull hs = ps[p];
                ffma2(ai[p], wi2, hs);
                ffma2(ao[p], wo2, hs);
                ffma2(au[p], wu2, hs);
                ffma2(afl[p], wf2, pl[p]);
                ffma2(afr[p], wf2, pr[p]);
            }
        }
        float bi = bh[j], bo = bh[150 + j], bu = bh[300 + j], bfv = bf[j];
#pragma unroll
        for (int p = 0; p < R/2; p++) {
            float2 fi = unpack2(ai[p]), fo = unpack2(ao[p]), fu = unpack2(au[p]);
            float2 ffl = unpack2(afl[p]), ffr = unpack2(afr[p]);
#pragma unroll
            for (int h = 0; h < 2; h++) {
                int r = 2 * p + h;
                float iv = sigf((h ? fi.y : fi.x) + bi);
                float ov = sigf((h ? fo.y : fo.x) + bo);
                float uv = tanhf((h ? fu.y : fu.x) + bu);
                float fl = sigf((h ? ffl.y : ffl.x) + bfv);
                float fr = sigf((h ? ffr.y : ffr.x) + bfv);
                int t = s_t[r];
                float c = iv * uv + fl * g_C[t][s_li[r]][j] + fr * g_C[t][s_ri[r]][j];
                g_C[t][s_k[r]][j] = c;
                g_H[t][s_k[r]][j] = ov * tanhf(c);
            }
        }
    }
}

// ---------------------------------------------------------------------------
// Attention scores: one warp per (side, node) dot product of length 150.
// ---------------------------------------------------------------------------
__global__ void score_kernel()
{
    int wid = (blockIdx.x * blockDim.x + threadIdx.x) >> 5;
    int lane = threadIdx.x & 31;
    if (wid >= 2 * NNODES) return;
    int side = wid / NNODES;
    int node = wid - side * NNODES;
    int qt = side;
    int rt = 1 - side;
    float sum = 0.f;
    for (int k = lane; k < MEM; k += 32)
        sum += g_H[qt][NNODES - 1][k] * g_H[rt][node][k];
#pragma unroll
    for (int off = 16; off; off >>= 1) sum += __shfl_xor_sync(0xffffffffu, sum, off);
    if (lane == 0) g_s[side][node] = sum;
}

// ---------------------------------------------------------------------------
// Softmax normalizers (max + 1/sumexp) for both score vectors. One block.
// ---------------------------------------------------------------------------
__global__ void reduce_kernel()
{
    __shared__ float red[8];
    __shared__ float bc;
    const int tid = threadIdx.x;
    const int lane = tid & 31, w = tid >> 5;
    for (int side = 0; side < 2; side++) {
        float m = -1e30f;
        for (int i = tid; i < NNODES; i += 256) m = fmaxf(m, g_s[side][i]);
#pragma unroll
        for (int off = 16; off; off >>= 1) m = fmaxf(m, __shfl_xor_sync(0xffffffffu, m, off));
        if (lane == 0) red[w] = m;
        __syncthreads();
        if (tid == 0) {
            float mm = red[0];
            for (int i = 1; i < 8; i++) mm = fmaxf(mm, red[i]);
            bc = mm;
        }
        __syncthreads();
        float mx = bc;
        float s = 0.f;
        for (int i = tid; i < NNODES; i += 256) s += expf(g_s[side][i] - mx);
#pragma unroll
        for (int off = 16; off; off >>= 1) s += __shfl_xor_sync(0xffffffffu, s, off);
        __syncthreads();
        if (lane == 0) red[w] = s;
        __syncthreads();
        if (tid == 0) {
            float tot = 0.f;
            for (int i = 0; i < 8; i++) tot += red[i];
            g_red[side * 2] = mx;
            g_red[side * 2 + 1] = 1.f / tot;
        }
        __syncthreads();
    }
}

// ---------------------------------------------------------------------------
// Weighted sums: beta_last = softmax(s_l) @ Hr; alpha_last = softmax(s_r) @ Hl.
// Deterministic: each block writes its own partial slot; summed later in order.
// ---------------------------------------------------------------------------
#define ACHUNK 128
__global__ __launch_bounds__(160) void attsum_kernel()
{
    __shared__ float w[ACHUNK];
    const int side = blockIdx.y;
    const int rt = 1 - side;
    const int tid = threadIdx.x;
    const int j0 = blockIdx.x * ACHUNK;
    float mx = g_red[side * 2], inv = g_red[side * 2 + 1];
    for (int jj = tid; jj < ACHUNK; jj += 160) {
        int jg = j0 + jj;
        w[jj] = (jg < NNODES) ? expf(g_s[side][jg] - mx) * inv : 0.f;
    }
    __syncthreads();
    if (tid < MEM) {
        float p = 0.f;
        int lim = min(ACHUNK, NNODES - j0);
        for (int jj = 0; jj < lim; jj++)
            p = fmaf(w[jj], g_H[rt][j0 + jj][tid], p);
        g_part[side][blockIdx.x][tid] = p;
    }
}

// ---------------------------------------------------------------------------
// Final head: v_l/v_r last rows, feature MLP, log_softmax. One block.
// ---------------------------------------------------------------------------
__global__ __launch_bounds__(160) void final_kernel(
    const float* __restrict__ Wa, const float* __restrict__ ba,
    const float* __restrict__ Wwh, const float* __restrict__ bwh,
    const float* __restrict__ Wwp, const float* __restrict__ bwp,
    float* __restrict__ out)
{
    __shared__ float q0[MEM], q1[MEM], beta[MEM], alpha[MEM];
    __shared__ float slh[MEM], srh[MEM], hid[HIDD], lg[NCLS];
    const int tid = threadIdx.x;
    if (tid < MEM) {
        q0[tid] = g_H[0][NNODES - 1][tid];
        q1[tid] = g_H[1][NNODES - 1][tid];
        float b = 0.f, a = 0.f;
        for (int p = 0; p < 32; p++) { b += g_part[0][p][tid]; a += g_part[1][p][tid]; }
        beta[tid] = b; alpha[tid] = a;
    }
    __syncthreads();
    if (tid < MEM) {
        float lh = ba[tid], rh = ba[tid];
        for (int k = 0; k < MEM; k++) {
            float w1 = Wa[k * MEM + tid];
            float w2 = Wa[(MEM + k) * MEM + tid];
            lh += q0[k] * w1 + beta[k] * w2;
            rh += q1[k] * w1 + alpha[k] * w2;
        }
        slh[tid] = lh; srh[tid] = rh;
    }
    __syncthreads();
    if (tid < HIDD) {
        float acc = bwh[tid];
        for (int k = 0; k < MEM; k++) {
            float pr = slh[k] * srh[k];
            float ad = fabsf(slh[k] - srh[k]);
            acc += pr * Wwh[k * HIDD + tid] + ad * Wwh[(MEM + k) * HIDD + tid];
        }
        hid[tid] = 1.f / (1.f + expf(-acc));
    }
    __syncthreads();
    if (tid < NCLS) {
        float v = bwp[tid];
        for (int m = 0; m < HIDD; m++) v += hid[m] * Wwp[m * NCLS + tid];
        lg[tid] = v;
    }
    __syncthreads();
    if (tid < NCLS) {
        float mx = lg[0];
        for (int c = 1; c < NCLS; c++) mx = fmaxf(mx, lg[c]);
        float s = 0.f;
        for (int c = 0; c < NCLS; c++) s += expf(lg[c] - mx);
        out[tid] = lg[tid] - mx - logf(s);
    }
}

// ---------------------------------------------------------------------------
extern "C" void kernel_launch(void* const* d_in, const int* in_sizes, int n_in,
                              void* d_out, int out_size)
{
    const int*   ltok = (const int*)d_in[0];
    const int*   rtok = (const int*)d_in[1];
    const int*   lidx = (const int*)d_in[2];
    const int*   ridx = (const int*)d_in[3];
    const float* emb  = (const float*)d_in[4];
    const float* Wx   = (const float*)d_in[5];
    const float* bx   = (const float*)d_in[6];
    const float* Wh   = (const float*)d_in[7];
    const float* bhh  = (const float*)d_in[8];
    // d_in[9] = W_fx, d_in[10] = b_fx : unused by the reference
    const float* Wf   = (const float*)d_in[11];
    const float* bf   = (const float*)d_in[12];
    const float* Wa   = (const float*)d_in[13];
    const float* ba   = (const float*)d_in[14];
    const float* Wwh  = (const float*)d_in[15];
    const float* bwh  = (const float*)d_in[16];
    const float* Wwp  = (const float*)d_in[17];
    const float* bwp  = (const float*)d_in[18];
    float* out = (float*)d_out;

    leaf_kernel<<<256, 160>>>(ltok, rtok, emb, Wx, bx, bhh);

    // levels: (e0, P, R, blocks=2P/R)
    level_kernel<8><<<256, 160>>>(lidx, ridx, Wh, bhh, Wf, bf, 0,    1024);
    level_kernel<4><<<256, 160>>>(lidx, ridx, Wh, bhh, Wf, bf, 1024, 512);
    level_kernel<4><<<128, 160>>>(lidx, ridx, Wh, bhh, Wf, bf, 1536, 256);
    level_kernel<2><<<128, 160>>>(lidx, ridx, Wh, bhh, Wf, bf, 1792, 128);
    level_kernel<2><<<64,  160>>>(lidx, ridx, Wh, bhh, Wf, bf, 1920, 64);
    level_kernel<2><<<32,  160>>>(lidx, ridx, Wh, bhh, Wf, bf, 1984, 32);
    level_kernel<2><<<16,  160>>>(lidx, ridx, Wh, bhh, Wf, bf, 2016, 16);
    level_kernel<2><<<8,   160>>>(lidx, ridx, Wh, bhh, Wf, bf, 2032, 8);
    level_kernel<2><<<4,   160>>>(lidx, ridx, Wh, bhh, Wf, bf, 2040, 4);
    level_kernel<2><<<2,   160>>>(lidx, ridx, Wh, bhh, Wf, bf, 2044, 2);
    level_kernel<2><<<1,   160>>>(lidx, ridx, Wh, bhh, Wf, bf, 2046, 1);

    score_kernel<<<1024, 256>>>();
    reduce_kernel<<<1, 256>>>();
    attsum_kernel<<<dim3(32, 2), 160>>>();
    final_kernel<<<1, 160>>>(Wa, ba, Wwh, bwh, Wwp, bwp, out);
}

// round 4
// speedup vs baseline: 2.3481x; 1.3046x over previous
#include <cuda_runtime.h>
#include <math.h>

#define LLEAF 2048
#define NNODES 4095
#define MEM 150
#define IN_DIM 300
#define HIDD 50
#define NCLS 5
#define HSTR 152

typedef unsigned long long ull;

// Scratch (device globals: no allocations allowed)
__device__ float g_C[2][NNODES][HSTR];
__device__ float g_H[2][NNODES][HSTR];
__device__ float g_s[2][NNODES];
__device__ float g_red[4];              // maxl, invsuml, maxr, invsumr
__device__ float g_part[2][32][HSTR];   // partial attention sums (deterministic)

__device__ __forceinline__ float sigf(float x) { return 1.f / (1.f + expf(-x)); }

__device__ __forceinline__ ull pack2(float a, float b) {
    ull r; asm("mov.b64 %0, {%1,%2};" : "=l"(r) : "f"(a), "f"(b)); return r;
}
__device__ __forceinline__ void ffma2(ull& d, ull a, ull b) {
    asm("fma.rn.f32x2 %0, %1, %2, %0;" : "+l"(d) : "l"(a), "l"(b));
}
__device__ __forceinline__ float2 unpack2(ull v) {
    float2 f; asm("mov.b64 {%0,%1}, %2;" : "=f"(f.x), "=f"(f.y) : "l"(v)); return f;
}

// ---------------------------------------------------------------------------
// Leaf kernel: 16 leaves per block, transposed shared activations, f32x2 FMA,
// split-K over S thread-groups, KU-chunked weight loads for MLP.
// xs and the split-K reduction buffer share one smem region (disjoint lifetimes).
// ---------------------------------------------------------------------------
#define RLEAF 16
#define XPAD 18
template <int S>
__global__ __launch_bounds__(160 * S) void leaf_kernel(
    const int* __restrict__ ltok, const int* __restrict__ rtok,
    const float* __restrict__ emb, const float* __restrict__ Wx,
    const float* __restrict__ bx, const float* __restrict__ bh)
{
    constexpr int NA = 3 * RLEAF / 2;      // 24 ull accumulators
    constexpr int KR = IN_DIM / S;         // k-range per group
    constexpr int KU = 5;
    constexpr int XS_FLOATS = IN_DIM * XPAD;               // 5400
    constexpr int RED_FLOATS = (S - 1) * 160 * NA * 2;     // 7680 for S=2
    constexpr int SBUF = XS_FLOATS > RED_FLOATS ? XS_FLOATS : RED_FLOATS;
    __shared__ __align__(16) float sbuf[SBUF];             // xs THEN red
    __shared__ int toks[RLEAF];
    float (*xs)[XPAD] = reinterpret_cast<float (*)[XPAD]>(sbuf);
    float* red = sbuf;

    const int tid = threadIdx.x;
    const int grp = tid / 160;
    const int j = tid - grp * 160;
    const int t = blockIdx.x >> 7;       // tree (0/1), 128 blocks per tree
    const int g = blockIdx.x & 127;
    const int leaf0 = g * RLEAF;
    const int* tok = t ? rtok : ltok;

    if (tid < RLEAF) toks[tid] = tok[leaf0 + tid];
    __syncthreads();
    for (int idx = tid; idx < RLEAF * IN_DIM; idx += 160 * S) {
        int r = idx / IN_DIM, k = idx - r * IN_DIM;
        xs[k][r] = emb[toks[r] * IN_DIM + k];
    }
    __syncthreads();

    ull acc[NA];
#pragma unroll
    for (int a = 0; a < NA; a++) acc[a] = 0ull;

    if (j < MEM) {
        const int kb = grp * KR;
        for (int kc = 0; kc < KR; kc += KU) {
            float w[KU][3];
#pragma unroll
            for (int q = 0; q < KU; q++) {
                int k = kb + kc + q;
                w[q][0] = Wx[k * 450 + j];
                w[q][1] = Wx[k * 450 + 150 + j];
                w[q][2] = Wx[k * 450 + 300 + j];
            }
#pragma unroll
            for (int q = 0; q < KU; q++) {
                int k = kb + kc + q;
                ull wi2 = pack2(w[q][0], w[q][0]);
                ull wo2 = pack2(w[q][1], w[q][1]);
                ull wu2 = pack2(w[q][2], w[q][2]);
                const ull* px = reinterpret_cast<const ull*>(&xs[k][0]);
#pragma unroll
                for (int p = 0; p < RLEAF / 2; p++) {
                    ull xv = px[p];
                    ffma2(acc[0 * (RLEAF/2) + p], wi2, xv);
                    ffma2(acc[1 * (RLEAF/2) + p], wo2, xv);
                    ffma2(acc[2 * (RLEAF/2) + p], wu2, xv);
                }
            }
        }
    }
    __syncthreads();                       // xs lifetime ends; red begins

    // split-K reduction through shared memory (deterministic)
    float2 fa[NA];
#pragma unroll
    for (int a = 0; a < NA; a++) fa[a] = unpack2(acc[a]);
    if (grp > 0 && j < MEM) {
        float2* dst = reinterpret_cast<float2*>(&red[((grp - 1) * 160 + j) * NA * 2]);
#pragma unroll
        for (int a = 0; a < NA; a++) dst[a] = fa[a];
    }
    __syncthreads();
    if (grp == 0 && j < MEM) {
#pragma unroll
        for (int s = 1; s < S; s++) {
            const float2* src = reinterpret_cast<const float2*>(&red[((s - 1) * 160 + j) * NA * 2]);
#pragma unroll
            for (int a = 0; a < NA; a++) { float2 v = src[a]; fa[a].x += v.x; fa[a].y += v.y; }
        }
        float bi = bx[j] + bh[j];
        float bo = bx[150 + j] + bh[150 + j];
        float bu = bx[300 + j] + bh[300 + j];
#pragma unroll
        for (int p = 0; p < RLEAF / 2; p++) {
            float2 fi = fa[0 * (RLEAF/2) + p], fo = fa[1 * (RLEAF/2) + p], fu = fa[2 * (RLEAF/2) + p];
#pragma unroll
            for (int h = 0; h < 2; h++) {
                float iv = sigf((h ? fi.y : fi.x) + bi);
                float ov = sigf((h ? fo.y : fo.x) + bo);
                float uv = tanhf((h ? fu.y : fu.x) + bu);
                float c = iv * uv;
                g_C[t][leaf0 + 2 * p + h][j] = c;
                g_H[t][leaf0 + 2 * p + h][j] = ov * tanhf(c);
            }
        }
    }
}

// ---------------------------------------------------------------------------
// Level kernel: R internal nodes per block (R | 2P exactly), transposed
// shared activations, f32x2 FMA, split-K over S groups, KU-chunked loads.
// ---------------------------------------------------------------------------
template <int R, int S>
__global__ __launch_bounds__(160 * S) void level_kernel(
    const int* __restrict__ lidx, const int* __restrict__ ridx,
    const float* __restrict__ Wh, const float* __restrict__ bh,
    const float* __restrict__ Wf, const float* __restrict__ bf,
    int e0, int P)
{
    constexpr int NA = 5 * R / 2;
    constexpr int KR = MEM / S;            // 75 for S=2
    constexpr int KU = 5;
    __shared__ __align__(16) float ss[MEM][R + 2], sl[MEM][R + 2], sr[MEM][R + 2];
    __shared__ __align__(16) float red[(S - 1) * 160 * NA * 2];
    __shared__ int s_li[R], s_ri[R], s_t[R], s_k[R];
    const int tid = threadIdx.x;
    const int grp = tid / 160;
    const int j = tid - grp * 160;

    if (tid < R) {
        int u = blockIdx.x * R + tid;
        int t = u / P;
        int e = e0 + (u - t * P);
        s_t[tid] = t;
        s_k[tid] = LLEAF + e;
        s_li[tid] = lidx[e];
        s_ri[tid] = ridx[e];
    }
    __syncthreads();
    for (int idx = tid; idx < R * MEM; idx += 160 * S) {
        int r = idx / MEM, k = idx - r * MEM;
        float a = g_H[s_t[r]][s_li[r]][k];
        float b = g_H[s_t[r]][s_ri[r]][k];
        sl[k][r] = a; sr[k][r] = b; ss[k][r] = a + b;
    }
    __syncthreads();

    ull acc[NA];
#pragma unroll
    for (int a = 0; a < NA; a++) acc[a] = 0ull;

    if (j < MEM) {
        const int kb = grp * KR;
        for (int kc = 0; kc < KR; kc += KU) {
            float w[KU][4];
#pragma unroll
            for (int q = 0; q < KU; q++) {
                int k = kb + kc + q;
                w[q][0] = Wh[k * 450 + j];
                w[q][1] = Wh[k * 450 + 150 + j];
                w[q][2] = Wh[k * 450 + 300 + j];
                w[q][3] = Wf[k * 150 + j];
            }
#pragma unroll
            for (int q = 0; q < KU; q++) {
                int k = kb + kc + q;
                ull wi2 = pack2(w[q][0], w[q][0]);
                ull wo2 = pack2(w[q][1], w[q][1]);
                ull wu2 = pack2(w[q][2], w[q][2]);
                ull wf2 = pack2(w[q][3], w[q][3]);
                const ull* ps = reinterpret_cast<const ull*>(&ss[k][0]);
                const ull* pl = reinterpret_cast<const ull*>(&sl[k][0]);
                const ull* pr = reinterpret_cast<const ull*>(&sr[k][0]);
#pragma unroll
                for (int p = 0; p < R / 2; p++) {
                    ull hs = ps[p];
                    ffma2(acc[0 * (R/2) + p], wi2, hs);
                    ffma2(acc[1 * (R/2) + p], wo2, hs);
                    ffma2(acc[2 * (R/2) + p], wu2, hs);
                    ffma2(acc[3 * (R/2) + p], wf2, pl[p]);
                    ffma2(acc[4 * (R/2) + p], wf2, pr[p]);
                }
            }
        }
    }

    float2 fa[NA];
#pragma unroll
    for (int a = 0; a < NA; a++) fa[a] = unpack2(acc[a]);
    if (grp > 0 && j < MEM) {
        float2* dst = reinterpret_cast<float2*>(&red[((grp - 1) * 160 + j) * NA * 2]);
#pragma unroll
        for (int a = 0; a < NA; a++) dst[a] = fa[a];
    }
    __syncthreads();
    if (grp == 0 && j < MEM) {
#pragma unroll
        for (int s = 1; s < S; s++) {
            const float2* src = reinterpret_cast<const float2*>(&red[((s - 1) * 160 + j) * NA * 2]);
#pragma unroll
            for (int a = 0; a < NA; a++) { float2 v = src[a]; fa[a].x += v.x; fa[a].y += v.y; }
        }
        float bi = bh[j], bo = bh[150 + j], bu = bh[300 + j], bfv = bf[j];
#pragma unroll
        for (int p = 0; p < R / 2; p++) {
            float2 fi = fa[0 * (R/2) + p], fo = fa[1 * (R/2) + p], fu = fa[2 * (R/2) + p];
            float2 ffl = fa[3 * (R/2) + p], ffr = fa[4 * (R/2) + p];
#pragma unroll
            for (int h = 0; h < 2; h++) {
                int r = 2 * p + h;
                float iv = sigf((h ? fi.y : fi.x) + bi);
                float ov = sigf((h ? fo.y : fo.x) + bo);
                float uv = tanhf((h ? fu.y : fu.x) + bu);
                float fl = sigf((h ? ffl.y : ffl.x) + bfv);
                float fr = sigf((h ? ffr.y : ffr.x) + bfv);
                int t = s_t[r];
                float c = iv * uv + fl * g_C[t][s_li[r]][j] + fr * g_C[t][s_ri[r]][j];
                g_C[t][s_k[r]][j] = c;
                g_H[t][s_k[r]][j] = ov * tanhf(c);
            }
        }
    }
}

// ---------------------------------------------------------------------------
// Attention scores: one warp per (side, node) dot product of length 150.
// ---------------------------------------------------------------------------
__global__ void score_kernel()
{
    int wid = (blockIdx.x * blockDim.x + threadIdx.x) >> 5;
    int lane = threadIdx.x & 31;
    if (wid >= 2 * NNODES) return;
    int side = wid / NNODES;
    int node = wid - side * NNODES;
    int qt = side;
    int rt = 1 - side;
    float sum = 0.f;
    for (int k = lane; k < MEM; k += 32)
        sum += g_H[qt][NNODES - 1][k] * g_H[rt][node][k];
#pragma unroll
    for (int off = 16; off; off >>= 1) sum += __shfl_xor_sync(0xffffffffu, sum, off);
    if (lane == 0) g_s[side][node] = sum;
}

// ---------------------------------------------------------------------------
// Softmax normalizers (max + 1/sumexp) for both score vectors. One block.
// ---------------------------------------------------------------------------
__global__ void reduce_kernel()
{
    __shared__ float red[8];
    __shared__ float bc;
    const int tid = threadIdx.x;
    const int lane = tid & 31, w = tid >> 5;
    for (int side = 0; side < 2; side++) {
        float m = -1e30f;
        for (int i = tid; i < NNODES; i += 256) m = fmaxf(m, g_s[side][i]);
#pragma unroll
        for (int off = 16; off; off >>= 1) m = fmaxf(m, __shfl_xor_sync(0xffffffffu, m, off));
        if (lane == 0) red[w] = m;
        __syncthreads();
        if (tid == 0) {
            float mm = red[0];
            for (int i = 1; i < 8; i++) mm = fmaxf(mm, red[i]);
            bc = mm;
        }
        __syncthreads();
        float mx = bc;
        float s = 0.f;
        for (int i = tid; i < NNODES; i += 256) s += expf(g_s[side][i] - mx);
#pragma unroll
        for (int off = 16; off; off >>= 1) s += __shfl_xor_sync(0xffffffffu, s, off);
        __syncthreads();
        if (lane == 0) red[w] = s;
        __syncthreads();
        if (tid == 0) {
            float tot = 0.f;
            for (int i = 0; i < 8; i++) tot += red[i];
            g_red[side * 2] = mx;
            g_red[side * 2 + 1] = 1.f / tot;
        }
        __syncthreads();
    }
}

// ---------------------------------------------------------------------------
// Weighted sums: beta_last = softmax(s_l) @ Hr; alpha_last = softmax(s_r) @ Hl.
// Deterministic: each block writes its own partial slot; summed later in order.
// ---------------------------------------------------------------------------
#define ACHUNK 128
__global__ __launch_bounds__(160) void attsum_kernel()
{
    __shared__ float w[ACHUNK];
    const int side = blockIdx.y;
    const int rt = 1 - side;
    const int tid = threadIdx.x;
    const int j0 = blockIdx.x * ACHUNK;
    float mx = g_red[side * 2], inv = g_red[side * 2 + 1];
    for (int jj = tid; jj < ACHUNK; jj += 160) {
        int jg = j0 + jj;
        w[jj] = (jg < NNODES) ? expf(g_s[side][jg] - mx) * inv : 0.f;
    }
    __syncthreads();
    if (tid < MEM) {
        float p = 0.f;
        int lim = min(ACHUNK, NNODES - j0);
        for (int jj = 0; jj < lim; jj++)
            p = fmaf(w[jj], g_H[rt][j0 + jj][tid], p);
        g_part[side][blockIdx.x][tid] = p;
    }
}

// ---------------------------------------------------------------------------
// Final head: v_l/v_r last rows, feature MLP, log_softmax. One block.
// ---------------------------------------------------------------------------
__global__ __launch_bounds__(160) void final_kernel(
    const float* __restrict__ Wa, const float* __restrict__ ba,
    const float* __restrict__ Wwh, const float* __restrict__ bwh,
    const float* __restrict__ Wwp, const float* __restrict__ bwp,
    float* __restrict__ out)
{
    __shared__ float q0[MEM], q1[MEM], beta[MEM], alpha[MEM];
    __shared__ float slh[MEM], srh[MEM], hid[HIDD], lg[NCLS];
    const int tid = threadIdx.x;
    if (tid < MEM) {
        q0[tid] = g_H[0][NNODES - 1][tid];
        q1[tid] = g_H[1][NNODES - 1][tid];
        float b = 0.f, a = 0.f;
        for (int p = 0; p < 32; p++) { b += g_part[0][p][tid]; a += g_part[1][p][tid]; }
        beta[tid] = b; alpha[tid] = a;
    }
    __syncthreads();
    if (tid < MEM) {
        float lh = ba[tid], rh = ba[tid];
        for (int k = 0; k < MEM; k++) {
            float w1 = Wa[k * MEM + tid];
            float w2 = Wa[(MEM + k) * MEM + tid];
            lh += q0[k] * w1 + beta[k] * w2;
            rh += q1[k] * w1 + alpha[k] * w2;
        }
        slh[tid] = lh; srh[tid] = rh;
    }
    __syncthreads();
    if (tid < HIDD) {
        float acc = bwh[tid];
        for (int k = 0; k < MEM; k++) {
            float pr = slh[k] * srh[k];
            float ad = fabsf(slh[k] - srh[k]);
            acc += pr * Wwh[k * HIDD + tid] + ad * Wwh[(MEM + k) * HIDD + tid];
        }
        hid[tid] = 1.f / (1.f + expf(-acc));
    }
    __syncthreads();
    if (tid < NCLS) {
        float v = bwp[tid];
        for (int m = 0; m < HIDD; m++) v += hid[m] * Wwp[m * NCLS + tid];
        lg[tid] = v;
    }
    __syncthreads();
    if (tid < NCLS) {
        float mx = lg[0];
        for (int c = 1; c < NCLS; c++) mx = fmaxf(mx, lg[c]);
        float s = 0.f;
        for (int c = 0; c < NCLS; c++) s += expf(lg[c] - mx);
        out[tid] = lg[tid] - mx - logf(s);
    }
}

// ---------------------------------------------------------------------------
extern "C" void kernel_launch(void* const* d_in, const int* in_sizes, int n_in,
                              void* d_out, int out_size)
{
    const int*   ltok = (const int*)d_in[0];
    const int*   rtok = (const int*)d_in[1];
    const int*   lidx = (const int*)d_in[2];
    const int*   ridx = (const int*)d_in[3];
    const float* emb  = (const float*)d_in[4];
    const float* Wx   = (const float*)d_in[5];
    const float* bx   = (const float*)d_in[6];
    const float* Wh   = (const float*)d_in[7];
    const float* bhh  = (const float*)d_in[8];
    // d_in[9] = W_fx, d_in[10] = b_fx : unused by the reference
    const float* Wf   = (const float*)d_in[11];
    const float* bf   = (const float*)d_in[12];
    const float* Wa   = (const float*)d_in[13];
    const float* ba   = (const float*)d_in[14];
    const float* Wwh  = (const float*)d_in[15];
    const float* bwh  = (const float*)d_in[16];
    const float* Wwp  = (const float*)d_in[17];
    const float* bwp  = (const float*)d_in[18];
    float* out = (float*)d_out;

    leaf_kernel<2><<<256, 320>>>(ltok, rtok, emb, Wx, bx, bhh);

    // levels: blocks = 2P/R, 320 threads (split-K=2)
    level_kernel<8, 2><<<256, 320>>>(lidx, ridx, Wh, bhh, Wf, bf, 0,    1024);
    level_kernel<4, 2><<<256, 320>>>(lidx, ridx, Wh, bhh, Wf, bf, 1024, 512);
    level_kernel<4, 2><<<128, 320>>>(lidx, ridx, Wh, bhh, Wf, bf, 1536, 256);
    level_kernel<2, 2><<<128, 320>>>(lidx, ridx, Wh, bhh, Wf, bf, 1792, 128);
    level_kernel<2, 2><<<64,  320>>>(lidx, ridx, Wh, bhh, Wf, bf, 1920, 64);
    level_kernel<2, 2><<<32,  320>>>(lidx, ridx, Wh, bhh, Wf, bf, 1984, 32);
    level_kernel<2, 2><<<16,  320>>>(lidx, ridx, Wh, bhh, Wf, bf, 2016, 16);
    level_kernel<2, 2><<<8,   320>>>(lidx, ridx, Wh, bhh, Wf, bf, 2032, 8);
    level_kernel<2, 2><<<4,   320>>>(lidx, ridx, Wh, bhh, Wf, bf, 2040, 4);
    level_kernel<2, 2><<<2,   320>>>(lidx, ridx, Wh, bhh, Wf, bf, 2044, 2);
    level_kernel<2, 2><<<1,   320>>>(lidx, ridx, Wh, bhh, Wf, bf, 2046, 1);

    score_kernel<<<1024, 256>>>();
    reduce_kernel<<<1, 256>>>();
    attsum_kernel<<<dim3(32, 2), 160>>>();
    final_kernel<<<1, 160>>>(Wa, ba, Wwh, bwh, Wwp, bwp, out);
}

// round 5
// speedup vs baseline: 2.4235x; 1.0321x over previous
#include <cuda_runtime.h>
#include <math.h>

#define LLEAF 2048
#define NNODES 4095
#define MEM 150
#define IN_DIM 300
#define HIDD 50
#define NCLS 5
#define HSTR 152
#define NTHR 480

typedef unsigned long long ull;

// Scratch (device globals: no allocations allowed)
__device__ float g_C[2][NNODES][HSTR];
__device__ float g_H[2][NNODES][HSTR];
__device__ float g_s[2][NNODES];
__device__ float g_red4[4];             // maxl, invsuml, maxr, invsumr
__device__ float g_part[2][32][HSTR];   // partial attention sums (deterministic)
__device__ unsigned g_gen;              // grid barrier generation (self-resetting)
__device__ unsigned g_cnt;              // grid barrier arrival count

__device__ __forceinline__ float sigf(float x) { return 1.f / (1.f + expf(-x)); }

__device__ __forceinline__ ull pack2(float a, float b) {
    ull r; asm("mov.b64 %0, {%1,%2};" : "=l"(r) : "f"(a), "f"(b)); return r;
}
__device__ __forceinline__ void ffma2(ull& d, ull a, ull b) {
    asm("fma.rn.f32x2 %0, %1, %2, %0;" : "+l"(d) : "l"(a), "l"(b));
}
__device__ __forceinline__ float2 unpack2(ull v) {
    float2 f; asm("mov.b64 {%0,%1}, %2;" : "=f"(f.x), "=f"(f.y) : "l"(v)); return f;
}

__device__ __forceinline__ unsigned ld_acq(unsigned* p) {
    unsigned v; asm volatile("ld.acquire.gpu.u32 %0, [%1];" : "=r"(v) : "l"(p) : "memory"); return v;
}
__device__ __forceinline__ void st_rel(unsigned* p, unsigned v) {
    asm volatile("st.release.gpu.u32 [%0], %1;" :: "l"(p), "r"(v) : "memory");
}

// Sense-reversing grid barrier. Leaves g_cnt == 0 after each use; g_gen grows
// monotonically across uses/replays, so replays are deterministic.
__device__ __forceinline__ void gbar() {
    __syncthreads();
    if (threadIdx.x == 0) {
        unsigned gen = ld_acq(&g_gen);
        __threadfence();
        if (atomicAdd(&g_cnt, 1u) == gridDim.x - 1u) {
            g_cnt = 0u;
            st_rel(&g_gen, gen + 1u);
        } else {
            while (ld_acq(&g_gen) == gen) __nanosleep(64);
        }
    }
    __syncthreads();
}

// ---------------------------------------------------------------------------
// Shared-memory union across phases
// ---------------------------------------------------------------------------
struct LvlS {                            // level phase (R <= 8)
    float ss[MEM][10], sl[MEM][10], sr[MEM][10];
    float2 buf[2][MEM][4];               // per-gate split-K wave buffer
    int li[8], ri[8], tt[8], kk[8];
};
struct LeafS {                           // leaf phase (16 leaves)
    float xs[IN_DIM][18];
    float2 buf[2][MEM][8];
    int toks[16];
};
struct AttS { float w[3][128]; };        // attsum phase (one chunk per group)
struct FinS {                            // reduce + final phases
    float q0[HSTR], q1[HSTR], beta[HSTR], alpha[HSTR];
    float slh[HSTR], srh[HSTR], hid[64], lg[8];
    float red[16]; float bc;
};
union SmemU { LvlS lvl; LeafS leaf; AttS att; FinS fin; };

// ---------------------------------------------------------------------------
// One level task: R nodes (R in {2,4,8}), split-K=3, f32x2 FMA, wave reduce.
// ---------------------------------------------------------------------------
template <int R>
__device__ __forceinline__ void level_task(
    SmemU& sm, int task, int e0, int P,
    const int* __restrict__ lidx, const int* __restrict__ ridx,
    const float* __restrict__ Wh, const float* __restrict__ bh,
    const float* __restrict__ Wf, const float* __restrict__ bf,
    int tid, int grp, int j)
{
    constexpr int NP = R / 2;
    if (tid < R) {
        int u = task * R + tid;
        int t = u / P;
        int e = e0 + (u - t * P);
        sm.lvl.tt[tid] = t;
        sm.lvl.kk[tid] = LLEAF + e;
        sm.lvl.li[tid] = lidx[e];
        sm.lvl.ri[tid] = ridx[e];
    }
    __syncthreads();
    for (int idx = tid; idx < R * MEM; idx += NTHR) {
        int r = idx / MEM, k = idx - r * MEM;
        float a = g_H[sm.lvl.tt[r]][sm.lvl.li[r]][k];
        float b = g_H[sm.lvl.tt[r]][sm.lvl.ri[r]][k];
        sm.lvl.sl[k][r] = a; sm.lvl.sr[k][r] = b; sm.lvl.ss[k][r] = a + b;
    }
    __syncthreads();

    ull acc[5 * NP];
#pragma unroll
    for (int a = 0; a < 5 * NP; a++) acc[a] = 0ull;

    if (j < MEM) {
        const int kb = grp * 50;
        for (int kc = 0; kc < 50; kc += 5) {
            float w[5][4];
#pragma unroll
            for (int q = 0; q < 5; q++) {
                int k = kb + kc + q;
                w[q][0] = Wh[k * 450 + j];
                w[q][1] = Wh[k * 450 + 150 + j];
                w[q][2] = Wh[k * 450 + 300 + j];
                w[q][3] = Wf[k * 150 + j];
            }
#pragma unroll
            for (int q = 0; q < 5; q++) {
                int k = kb + kc + q;
                ull wi2 = pack2(w[q][0], w[q][0]);
                ull wo2 = pack2(w[q][1], w[q][1]);
                ull wu2 = pack2(w[q][2], w[q][2]);
                ull wf2 = pack2(w[q][3], w[q][3]);
                const ull* ps = reinterpret_cast<const ull*>(&sm.lvl.ss[k][0]);
                const ull* pl = reinterpret_cast<const ull*>(&sm.lvl.sl[k][0]);
                const ull* pr = reinterpret_cast<const ull*>(&sm.lvl.sr[k][0]);
#pragma unroll
                for (int p = 0; p < NP; p++) {
                    ull hs = ps[p];
                    ffma2(acc[0 * NP + p], wi2, hs);
                    ffma2(acc[1 * NP + p], wo2, hs);
                    ffma2(acc[2 * NP + p], wu2, hs);
                    ffma2(acc[3 * NP + p], wf2, pl[p]);
                    ffma2(acc[4 * NP + p], wf2, pr[p]);
                }
            }
        }
    }

    float2 fa[5 * NP];
#pragma unroll
    for (int a = 0; a < 5 * NP; a++) fa[a] = unpack2(acc[a]);

#pragma unroll
    for (int gate = 0; gate < 5; gate++) {
        if (grp > 0 && j < MEM) {
#pragma unroll
            for (int p = 0; p < NP; p++) sm.lvl.buf[grp - 1][j][p] = fa[gate * NP + p];
        }
        __syncthreads();
        if (grp == 0 && j < MEM) {
#pragma unroll
            for (int s = 0; s < 2; s++)
#pragma unroll
                for (int p = 0; p < NP; p++) {
                    float2 v = sm.lvl.buf[s][j][p];
                    fa[gate * NP + p].x += v.x; fa[gate * NP + p].y += v.y;
                }
        }
        __syncthreads();
    }

    if (grp == 0 && j < MEM) {
        float bi = bh[j], bo = bh[150 + j], bu = bh[300 + j], bfv = bf[j];
#pragma unroll
        for (int p = 0; p < NP; p++) {
            float2 fi = fa[0 * NP + p], fo = fa[1 * NP + p], fu = fa[2 * NP + p];
            float2 ffl = fa[3 * NP + p], ffr = fa[4 * NP + p];
#pragma unroll
            for (int h = 0; h < 2; h++) {
                int r = 2 * p + h;
                float iv = sigf((h ? fi.y : fi.x) + bi);
                float ov = sigf((h ? fo.y : fo.x) + bo);
                float uv = tanhf((h ? fu.y : fu.x) + bu);
                float fl = sigf((h ? ffl.y : ffl.x) + bfv);
                float fr = sigf((h ? ffr.y : ffr.x) + bfv);
                int t = sm.lvl.tt[r];
                float c = iv * uv + fl * g_C[t][sm.lvl.li[r]][j] + fr * g_C[t][sm.lvl.ri[r]][j];
                g_C[t][sm.lvl.kk[r]][j] = c;
                g_H[t][sm.lvl.kk[r]][j] = ov * tanhf(c);
            }
        }
    }
    __syncthreads();
}

// ---------------------------------------------------------------------------
// The whole model as one persistent kernel with grid barriers.
// ---------------------------------------------------------------------------
__global__ __launch_bounds__(NTHR, 1) void fused_kernel(
    const int* __restrict__ ltok, const int* __restrict__ rtok,
    const int* __restrict__ lidx, const int* __restrict__ ridx,
    const float* __restrict__ emb,
    const float* __restrict__ Wx, const float* __restrict__ bx,
    const float* __restrict__ Wh, const float* __restrict__ bh,
    const float* __restrict__ Wf, const float* __restrict__ bf,
    const float* __restrict__ Wa, const float* __restrict__ ba,
    const float* __restrict__ Wwh, const float* __restrict__ bwh,
    const float* __restrict__ Wwp, const float* __restrict__ bwp,
    float* __restrict__ out)
{
    __shared__ SmemU sm;
    const int tid = threadIdx.x;
    const int bid = blockIdx.x;
    const int grp = tid / 160;
    const int j = tid - grp * 160;

    // ================= leaf phase: 256 tasks x 16 leaves ===================
    for (int task = bid; task < 256; task += gridDim.x) {
        int t = task >> 7;
        int g = task & 127;
        int leaf0 = g * 16;
        const int* tok = t ? rtok : ltok;
        if (tid < 16) sm.leaf.toks[tid] = tok[leaf0 + tid];
        __syncthreads();
        for (int idx = tid; idx < 16 * IN_DIM; idx += NTHR) {
            int r = idx / IN_DIM, k = idx - r * IN_DIM;
            sm.leaf.xs[k][r] = emb[sm.leaf.toks[r] * IN_DIM + k];
        }
        __syncthreads();

        ull acc[24];
#pragma unroll
        for (int a = 0; a < 24; a++) acc[a] = 0ull;
        if (j < MEM) {
            const int kb = grp * 100;
            for (int kc = 0; kc < 100; kc += 5) {
                float w[5][3];
#pragma unroll
                for (int q = 0; q < 5; q++) {
                    int k = kb + kc + q;
                    w[q][0] = Wx[k * 450 + j];
                    w[q][1] = Wx[k * 450 + 150 + j];
                    w[q][2] = Wx[k * 450 + 300 + j];
                }
#pragma unroll
                for (int q = 0; q < 5; q++) {
                    int k = kb + kc + q;
                    ull wi2 = pack2(w[q][0], w[q][0]);
                    ull wo2 = pack2(w[q][1], w[q][1]);
                    ull wu2 = pack2(w[q][2], w[q][2]);
                    const ull* px = reinterpret_cast<const ull*>(&sm.leaf.xs[k][0]);
#pragma unroll
                    for (int p = 0; p < 8; p++) {
                        ull xv = px[p];
                        ffma2(acc[p], wi2, xv);
                        ffma2(acc[8 + p], wo2, xv);
                        ffma2(acc[16 + p], wu2, xv);
                    }
                }
            }
        }
        float2 fa[24];
#pragma unroll
        for (int a = 0; a < 24; a++) fa[a] = unpack2(acc[a]);
#pragma unroll
        for (int gate = 0; gate < 3; gate++) {
            if (grp > 0 && j < MEM) {
#pragma unroll
                for (int p = 0; p < 8; p++) sm.leaf.buf[grp - 1][j][p] = fa[gate * 8 + p];
            }
            __syncthreads();
            if (grp == 0 && j < MEM) {
#pragma unroll
                for (int s = 0; s < 2; s++)
#pragma unroll
                    for (int p = 0; p < 8; p++) {
                        float2 v = sm.leaf.buf[s][j][p];
                        fa[gate * 8 + p].x += v.x; fa[gate * 8 + p].y += v.y;
                    }
            }
            __syncthreads();
        }
        if (grp == 0 && j < MEM) {
            float bi = bx[j] + bh[j];
            float bo = bx[150 + j] + bh[150 + j];
            float bu = bx[300 + j] + bh[300 + j];
#pragma unroll
            for (int p = 0; p < 8; p++) {
                float2 fi = fa[p], fo = fa[8 + p], fu = fa[16 + p];
#pragma unroll
                for (int h = 0; h < 2; h++) {
                    float iv = sigf((h ? fi.y : fi.x) + bi);
                    float ov = sigf((h ? fo.y : fo.x) + bo);
                    float uv = tanhf((h ? fu.y : fu.x) + bu);
                    float c = iv * uv;
                    g_C[t][leaf0 + 2 * p + h][j] = c;
                    g_H[t][leaf0 + 2 * p + h][j] = ov * tanhf(c);
                }
            }
        }
        __syncthreads();
    }
    gbar();

    // ================= 11 tree levels ======================================
    {
        const int e0s[11] = {0, 1024, 1536, 1792, 1920, 1984, 2016, 2032, 2040, 2044, 2046};
        const int Ps[11]  = {1024, 512, 256, 128, 64, 32, 16, 8, 4, 2, 1};
        for (int lev = 0; lev < 11; lev++) {
            int P = Ps[lev], e0 = e0s[lev];
            if (lev < 3) {
                int ntasks = 2 * P / 8;
                for (int task = bid; task < ntasks; task += gridDim.x)
                    level_task<8>(sm, task, e0, P, lidx, ridx, Wh, bh, Wf, bf, tid, grp, j);
            } else if (lev == 3) {
                int ntasks = 2 * P / 4;
                for (int task = bid; task < ntasks; task += gridDim.x)
                    level_task<4>(sm, task, e0, P, lidx, ridx, Wh, bh, Wf, bf, tid, grp, j);
            } else {
                int ntasks = 2 * P / 2;
                for (int task = bid; task < ntasks; task += gridDim.x)
                    level_task<2>(sm, task, e0, P, lidx, ridx, Wh, bh, Wf, bf, tid, grp, j);
            }
            gbar();
        }
    }

    // ================= attention scores ====================================
    {
        int wid = tid >> 5, lane = tid & 31;
        for (int d = bid * 15 + wid; d < 2 * NNODES; d += gridDim.x * 15) {
            int side = d / NNODES;
            int node = d - side * NNODES;
            int qt = side, rt = 1 - side;
            float sum = 0.f;
            for (int k = lane; k < MEM; k += 32)
                sum += g_H[qt][NNODES - 1][k] * g_H[rt][node][k];
#pragma unroll
            for (int off = 16; off; off >>= 1) sum += __shfl_xor_sync(0xffffffffu, sum, off);
            if (lane == 0) g_s[side][node] = sum;
        }
    }
    gbar();

    // ================= softmax normalizers (block 0) =======================
    if (bid == 0) {
        const int lane = tid & 31, w = tid >> 5;
        for (int side = 0; side < 2; side++) {
            float m = -1e30f;
            for (int i = tid; i < NNODES; i += NTHR) m = fmaxf(m, g_s[side][i]);
#pragma unroll
            for (int off = 16; off; off >>= 1) m = fmaxf(m, __shfl_xor_sync(0xffffffffu, m, off));
            if (lane == 0) sm.fin.red[w] = m;
            __syncthreads();
            if (tid == 0) {
                float mm = sm.fin.red[0];
                for (int i = 1; i < 15; i++) mm = fmaxf(mm, sm.fin.red[i]);
                sm.fin.bc = mm;
            }
            __syncthreads();
            float mx = sm.fin.bc;
            float s = 0.f;
            for (int i = tid; i < NNODES; i += NTHR) s += expf(g_s[side][i] - mx);
#pragma unroll
            for (int off = 16; off; off >>= 1) s += __shfl_xor_sync(0xffffffffu, s, off);
            __syncthreads();
            if (lane == 0) sm.fin.red[w] = s;
            __syncthreads();
            if (tid == 0) {
                float tot = 0.f;
                for (int i = 0; i < 15; i++) tot += sm.fin.red[i];
                g_red4[side * 2] = mx;
                g_red4[side * 2 + 1] = 1.f / tot;
            }
            __syncthreads();
        }
    }
    gbar();

    // ================= attention weighted sums =============================
    {
        int slot = bid * 3 + grp;              // 64 tasks: (side, chunk)
        bool active = slot < 64;
        int side = slot >> 5, chunk = slot & 31, rt = 1 - side;
        int j0 = chunk * 128;
        if (active) {
            float mx = g_red4[side * 2], inv = g_red4[side * 2 + 1];
            for (int jj = j; jj < 128; jj += 160) {
                int jg = j0 + jj;
                sm.att.w[grp][jj] = (jg < NNODES) ? expf(g_s[side][jg] - mx) * inv : 0.f;
            }
        }
        __syncthreads();
        if (active && j < MEM) {
            float p = 0.f;
            int lim = min(128, NNODES - j0);
            for (int jj = 0; jj < lim; jj++)
                p = fmaf(sm.att.w[grp][jj], g_H[rt][j0 + jj][j], p);
            g_part[side][chunk][j] = p;
        }
    }
    gbar();

    // ================= final head (block 0) ================================
    if (bid == 0) {
        if (tid < MEM) {
            sm.fin.q0[tid] = g_H[0][NNODES - 1][tid];
            sm.fin.q1[tid] = g_H[1][NNODES - 1][tid];
            float b = 0.f, a = 0.f;
            for (int p = 0; p < 32; p++) { b += g_part[0][p][tid]; a += g_part[1][p][tid]; }
            sm.fin.beta[tid] = b; sm.fin.alpha[tid] = a;
        }
        __syncthreads();
        if (tid < MEM) {
            float lh = ba[tid], rh = ba[tid];
            for (int k = 0; k < MEM; k++) {
                float w1 = Wa[k * MEM + tid];
                float w2 = Wa[(MEM + k) * MEM + tid];
                lh += sm.fin.q0[k] * w1 + sm.fin.beta[k] * w2;
                rh += sm.fin.q1[k] * w1 + sm.fin.alpha[k] * w2;
            }
            sm.fin.slh[tid] = lh; sm.fin.srh[tid] = rh;
        }
        __syncthreads();
        if (tid < HIDD) {
            float acc = bwh[tid];
            for (int k = 0; k < MEM; k++) {
                float pr = sm.fin.slh[k] * sm.fin.srh[k];
                float ad = fabsf(sm.fin.slh[k] - sm.fin.srh[k]);
                acc += pr * Wwh[k * HIDD + tid] + ad * Wwh[(MEM + k) * HIDD + tid];
            }
            sm.fin.hid[tid] = 1.f / (1.f + expf(-acc));
        }
        __syncthreads();
        if (tid < NCLS) {
            float v = bwp[tid];
            for (int m = 0; m < HIDD; m++) v += sm.fin.hid[m] * Wwp[m * NCLS + tid];
            sm.fin.lg[tid] = v;
        }
        __syncthreads();
        if (tid < NCLS) {
            float mx = sm.fin.lg[0];
            for (int c = 1; c < NCLS; c++) mx = fmaxf(mx, sm.fin.lg[c]);
            float s = 0.f;
            for (int c = 0; c < NCLS; c++) s += expf(sm.fin.lg[c] - mx);
            out[tid] = sm.fin.lg[tid] - mx - logf(s);
        }
    }
}

// ---------------------------------------------------------------------------
extern "C" void kernel_launch(void* const* d_in, const int* in_sizes, int n_in,
                              void* d_out, int out_size)
{
    const int*   ltok = (const int*)d_in[0];
    const int*   rtok = (const int*)d_in[1];
    const int*   lidx = (const int*)d_in[2];
    const int*   ridx = (const int*)d_in[3];
    const float* emb  = (const float*)d_in[4];
    const float* Wx   = (const float*)d_in[5];
    const float* bx   = (const float*)d_in[6];
    const float* Wh   = (const float*)d_in[7];
    const float* bhh  = (const float*)d_in[8];
    // d_in[9] = W_fx, d_in[10] = b_fx : unused by the reference
    const float* Wf   = (const float*)d_in[11];
    const float* bf   = (const float*)d_in[12];
    const float* Wa   = (const float*)d_in[13];
    const float* ba   = (const float*)d_in[14];
    const float* Wwh  = (const float*)d_in[15];
    const float* bwh  = (const float*)d_in[16];
    const float* Wwp  = (const float*)d_in[17];
    const float* bwp  = (const float*)d_in[18];
    float* out = (float*)d_out;

    int dev = 0, nsm = 0;
    cudaGetDevice(&dev);
    cudaDeviceGetAttribute(&nsm, cudaDevAttrMultiProcessorCount, dev);
    if (nsm <= 0) nsm = 64;   // conservative fallback, still correct

    fused_kernel<<<nsm, NTHR>>>(ltok, rtok, lidx, ridx, emb, Wx, bx, Wh, bhh,
                                Wf, bf, Wa, ba, Wwh, bwh, Wwp, bwp, out);
}